// round 14
// baseline (speedup 1.0000x reference)
#include <cuda_runtime.h>
#include <math.h>
#include <stdint.h>

#define NN 32
#define CC 64
#define TT 512
#define VV 25
#define C4V 16
#define W3V 75
#define COV 64
#define KSPLIT 32
#define KTOT (C4V*TT)
#define KCHUNK (KTOT/KSPLIT)  /* 256 */
#define TVTOT (TT*VV)
#define TVPAD 12850

typedef unsigned long long ull;

__device__ __forceinline__ ull pk2(float lo, float hi) {
    ull r; asm("mov.b64 %0, {%1,%2};" : "=l"(r) : "f"(lo), "f"(hi)); return r;
}
__device__ __forceinline__ ull fma2(ull a, ull b, ull c) {
    ull d; asm("fma.rn.f32x2 %0, %1, %2, %3;" : "=l"(d) : "l"(a), "l"(b), "l"(c)); return d;
}
__device__ __forceinline__ void unpk2(ull v, float& lo, float& hi) {
    asm("mov.b64 {%0,%1}, %2;" : "=f"(lo), "=f"(hi) : "l"(v));
}
__device__ __forceinline__ void cpa16(uint32_t s, const void* g) {
    asm volatile("cp.async.cg.shared.global [%0], [%1], 16;" :: "r"(s), "l"(g));
}
__device__ __forceinline__ void cpa_commit() {
    asm volatile("cp.async.commit_group;" ::: "memory");
}
template<int N> __device__ __forceinline__ void cpa_wait() {
    asm volatile("cp.async.wait_group %0;" :: "n"(N) : "memory");
}

__device__ float g_B[NN*C4V*TT*VV];
__device__ float g_L[(size_t)NN*TVPAD*64];
__device__ float g_Gpart[NN*KSPLIT*W3V*W3V];
__device__ float g_attp[NN*W3V*80];
__device__ float g_Aeff[3*W3V*80];

// ============================================================
__global__ void k0_init(const float* __restrict__ A, const float* __restrict__ PA,
                        const float* __restrict__ bd, const float* __restrict__ bc)
{
    int i = blockIdx.x*blockDim.x + threadIdx.x;
    if (i < 16875) {
        int k = i / 5625, r = i - k*5625;
        int w1 = r / 75, w2 = r - w1*75;
        g_Aeff[k*6000 + w1*80 + w2] = A[i] + PA[i];
    }
    if (i < 102400) {
        int ch = i & 63, rr = i >> 6;
        int n = rr / 50, row = rr - n*50;
        int tvp = (row < 25) ? row : (TVPAD - 25 + row - 25);
        float b = (ch < 16) ? bd[ch] : bc[ch-16];
        g_L[((size_t)n*TVPAD + tvp)*64 + ch] = b;
    }
}

// ============================================================
// K1 v2: x-splat fma2 (weight pairs load as ull directly)
// ============================================================
#define K1_TV 128
__global__ void __launch_bounds__(320) k1_conv80(
    const float* __restrict__ x,
    const float* __restrict__ Wa,
    const float* __restrict__ Wd, const float* __restrict__ bd,
    const float* __restrict__ Wc, const float* __restrict__ bc)
{
    extern __shared__ float sm[];
    float* sX = sm;
    float* sW = sm + 8192;
    float* sB = sm + 8192 + 5120;
    int tid = threadIdx.x;
    int n   = blockIdx.y;
    int tv0 = blockIdx.x * K1_TV;

    for (int i = tid; i < 5120; i += 320) {
        int c = i / 80, j = i - c*80;
        float w;
        if (j < 16)      w = Wd[j*CC + c];
        else if (j < 64) w = Wc[(j-16)*CC + c];
        else             w = Wa[(j-64)*CC + c];
        sW[i] = w;
    }
    if (tid < 80) sB[tid] = (tid < 16) ? bd[tid] : (tid < 64 ? bc[tid-16] : 0.f);

    const float* xp = x + (size_t)n*CC*TVTOT + tv0;
    for (int i = tid; i < 2048; i += 320) {
        int c = i >> 5, o = (i & 31) << 2;
        *reinterpret_cast<float4*>(&sX[c*128 + o]) =
            *reinterpret_cast<const float4*>(xp + (size_t)c*TVTOT + o);
    }
    __syncthreads();

    int jt = tid / 32;             // 0..9
    int tq = (tid & 31) << 2;
    // acc2[p][t]: channel pair p = (2p, 2p+1) within this jt group, tv t
    ull acc2[4][4];
#pragma unroll
    for (int a = 0; a < 4; a++)
#pragma unroll
        for (int b = 0; b < 4; b++) acc2[a][b] = 0ull;

#pragma unroll 4
    for (int c = 0; c < 64; c++) {
        float4 xf = *reinterpret_cast<const float4*>(&sX[c*128 + tq]);
        ull px[4];
        px[0] = pk2(xf.x, xf.x); px[1] = pk2(xf.y, xf.y);
        px[2] = pk2(xf.z, xf.z); px[3] = pk2(xf.w, xf.w);
        ulonglong2 w01 = *reinterpret_cast<const ulonglong2*>(&sW[c*80 + jt*8]);
        ulonglong2 w23 = *reinterpret_cast<const ulonglong2*>(&sW[c*80 + jt*8 + 4]);
        ull wp[4] = {w01.x, w01.y, w23.x, w23.y};
#pragma unroll
        for (int p = 0; p < 4; p++)
#pragma unroll
            for (int t = 0; t < 4; t++)
                acc2[p][t] = fma2(wp[p], px[t], acc2[p][t]);
    }

    // unpack: val[jj][t]
    float val[8][4];
#pragma unroll
    for (int p = 0; p < 4; p++)
#pragma unroll
        for (int t = 0; t < 4; t++)
            unpk2(acc2[p][t], val[2*p][t], val[2*p+1][t]);

    int j0 = jt*8;
    if (j0 < 64) {
        float b[8];
#pragma unroll
        for (int jj = 0; jj < 8; jj++) b[jj] = sB[j0+jj];
        float* gl = g_L + ((size_t)n*TVPAD + 25 + tv0 + tq)*64 + j0;
#pragma unroll
        for (int t4 = 0; t4 < 4; t4++) {
            float4 r0 = make_float4(val[0][t4]+b[0], val[1][t4]+b[1],
                                    val[2][t4]+b[2], val[3][t4]+b[3]);
            float4 r1 = make_float4(val[4][t4]+b[4], val[5][t4]+b[5],
                                    val[6][t4]+b[6], val[7][t4]+b[7]);
            *reinterpret_cast<float4*>(gl + (size_t)t4*64)     = r0;
            *reinterpret_cast<float4*>(gl + (size_t)t4*64 + 4) = r1;
        }
    } else {
#pragma unroll
        for (int jj = 0; jj < 8; jj++) {
            int o = j0 - 64 + jj;
            float4 r = make_float4(val[jj][0], val[jj][1], val[jj][2], val[jj][3]);
            *reinterpret_cast<float4*>(g_B + (size_t)(n*C4V + o)*TVTOT + tv0 + tq) = r;
        }
    }
}

// ============================================================
// K2 v4: symmetric Gram, 240 compute threads (2 k-subgroups x
// 120 upper-triangle tiles), smem combine, mirrored store.
// ============================================================
__global__ void k2_gram(const float* __restrict__ ba)
{
    __shared__ __align__(16) float tile[W3V*34];
    __shared__ float sAcc[120*25];
    int n  = blockIdx.y;
    int ks = blockIdx.x;
    int tid = threadIdx.x;

    int sub = 0, tw1 = 0, tw2 = 0;
    const bool act = tid < 240;
    if (act) {
        sub = tid / 120;
        int rem = tid - sub*120, i = 0;
        while (rem >= 15 - i) { rem -= 15 - i; i++; }
        tw1 = i; tw2 = i + rem;
    }

    ull acc2[5][5];
#pragma unroll
    for (int i = 0; i < 5; i++)
#pragma unroll
        for (int j = 0; j < 5; j++) acc2[i][j] = 0ull;

    int k0 = ks * KCHUNK;
    for (int kt = 0; kt < KCHUNK; kt += 32) {
        for (int i = tid; i < 32*W3V; i += 256) {
            int r = i / W3V, w = i - r*W3V;
            int k = k0 + kt + r;
            int o = k >> 9, t = k & 511;
            int win = w / VV, v = w - win*VV;
            int ts = t + win - 1;
            float val = ba[o];
            if (ts >= 0 && ts < TT)
                val += g_B[((size_t)(n*C4V + o)*TT + ts)*VV + v];
            tile[w*34 + r] = val;
        }
        __syncthreads();
        if (act) {
            const float* ta = &tile[(tw1*5)*34 + sub*16];
            const float* tb = &tile[(tw2*5)*34 + sub*16];
#pragma unroll
            for (int rp = 0; rp < 8; rp++) {
                ull pa[5], pb[5];
#pragma unroll
                for (int i = 0; i < 5; i++)
                    pa[i] = *reinterpret_cast<const ull*>(ta + i*34 + 2*rp);
#pragma unroll
                for (int j = 0; j < 5; j++)
                    pb[j] = *reinterpret_cast<const ull*>(tb + j*34 + 2*rp);
#pragma unroll
                for (int i = 0; i < 5; i++)
#pragma unroll
                    for (int j = 0; j < 5; j++)
                        acc2[i][j] = fma2(pa[i], pb[j], acc2[i][j]);
            }
        }
        __syncthreads();
    }
    // combine sub 1 into sub 0 via smem
    if (act && sub == 1) {
        int tt = tid - 120;
#pragma unroll
        for (int i = 0; i < 5; i++)
#pragma unroll
            for (int j = 0; j < 5; j++) {
                float lo, hi; unpk2(acc2[i][j], lo, hi);
                sAcc[tt*25 + i*5 + j] = lo + hi;
            }
    }
    __syncthreads();
    if (act && sub == 0) {
        float* gp = g_Gpart + (size_t)(n*KSPLIT + ks)*W3V*W3V;
#pragma unroll
        for (int i = 0; i < 5; i++)
#pragma unroll
            for (int j = 0; j < 5; j++) {
                float lo, hi; unpk2(acc2[i][j], lo, hi);
                float v = lo + hi + sAcc[tid*25 + i*5 + j];
                gp[(tw1*5+i)*W3V + (tw2*5+j)] = v;
                gp[(tw2*5+j)*W3V + (tw1*5+i)] = v;
            }
    }
}

// ============================================================
// K3a: parallel reduce of 32 partials into the p=0 slice.
// ============================================================
__global__ void k3a_reduce()
{
    int n = blockIdx.y;
    int i = blockIdx.x*256 + threadIdx.x;
    if (i >= W3V*W3V) return;
    const float* gp = g_Gpart + (size_t)n*KSPLIT*W3V*W3V + i;
    float s = 0.f;
#pragma unroll 8
    for (int p = 0; p < KSPLIT; p++)
        s += gp[(size_t)p*W3V*W3V];
    g_Gpart[(size_t)n*KSPLIT*W3V*W3V + i] = s;
}

// ============================================================
// K3b: softmax on reduced matrix -> padded att
// ============================================================
__global__ void k3b_softmax()
{
    __shared__ float sG[W3V*W3V];
    int n = blockIdx.x, tid = threadIdx.x;
    const float* gr = g_Gpart + (size_t)n*KSPLIT*W3V*W3V;
    for (int i = tid; i < W3V*W3V; i += 256)
        sG[i] = gr[i] * (1.0f / (float)W3V);
    __syncthreads();
    if (tid < W3V) {
        float mx = -1e30f;
        for (int w1 = 0; w1 < W3V; w1++) mx = fmaxf(mx, sG[w1*W3V + tid]);
        float sum = 0.f;
        for (int w1 = 0; w1 < W3V; w1++) {
            float e = expf(sG[w1*W3V + tid] - mx);
            sG[w1*W3V + tid] = e;
            sum += e;
        }
        float inv = 1.f / sum;
        for (int w1 = 0; w1 < W3V; w1++)
            g_attp[(size_t)n*6000 + w1*80 + tid] = sG[w1*W3V + tid] * inv;
    }
}

// ============================================================
// K4 v12 (unchanged from R13): TPB=8, 256 threads, 3 blocks/SM.
// ============================================================
#define SM_R    0       /* [75][76] = 5700 */
#define SM_LT   5700    /* [75][128] = 9600 ; X1 union after loop */
#define SM_WOT  15300   /* 3072 */
#define SM_BN   18372   /* 128 */
#define SM_TOT  18500   /* 74000 B */

__global__ void __launch_bounds__(256, 3) k4_main(
    const float* __restrict__ x,
    const float* __restrict__ Wo,  const float* __restrict__ bo,
    const float* __restrict__ gma, const float* __restrict__ bta,
    const float* __restrict__ mean,const float* __restrict__ var,
    float* __restrict__ out)
{
    extern __shared__ float sm[];
    uint32_t sbase = (uint32_t)__cvta_generic_to_shared(sm);
    int tid = threadIdx.x;
    int n  = blockIdx.x >> 6;
    int t0 = (blockIdx.x & 63) << 3;

    for (int i = tid; i < 3072; i += 256) {
        int kc = i >> 6, o = i & 63;
        sm[SM_WOT + i] = Wo[o*48 + kc];
    }
    if (tid < 64) {
        float sc = gma[tid] * rsqrtf(var[tid] + 1e-5f);
        sm[SM_BN + tid]      = sc;
        sm[SM_BN + 64 + tid] = (bo[tid] - mean[tid])*sc + bta[tid];
    }

    const float* gl = g_L + (size_t)n*TVPAD*64;

    auto issue_R = [&](int kk) {
        uint32_t rdst = sbase + SM_R*4;
        const float* rsrc = (kk == 0) ? (g_attp + (size_t)n*6000)
                                      : (g_Aeff + (size_t)(kk-1)*6000);
        for (int i = tid; i < 1425; i += 256) {
            int k = i / 19, q = (i - k*19) << 2;
            cpa16(rdst + (k*76 + q)*4, rsrc + k*80 + q);
        }
    };
    auto issue_LT = [&](int kk) {
        uint32_t ldst = sbase + SM_LT*4;
        for (int i = tid; i < 2400; i += 256) {
            int seg = i >> 2, q = (i & 3) << 2;
            int k  = seg >> 3, it = seg & 7;
            int win = (k*41) >> 10;
            int v   = k - win*25;
            int tvp = (t0 + it + win)*25 + v;
            cpa16(ldst + (k*128 + it*16 + q)*4,
                  gl + ((size_t)tvp << 6) + kk*16 + q);
        }
    };

    int w = tid >> 5, l = tid & 31;
    int mt = ((w >> 1) << 3) + (l >> 2);
    int nt = ((w & 1) << 2) + (l & 3);
    int m0 = mt << 2;
    int n0 = nt * 10;

    ull acc[4][5];
#pragma unroll
    for (int a = 0; a < 4; a++)
#pragma unroll
        for (int j = 0; j < 5; j++) acc[a][j] = 0ull;

    issue_R(0); issue_LT(0); cpa_commit();

    for (int kk = 0; kk < 4; kk++) {
        cpa_wait<0>();
        __syncthreads();

        const float* ltb = &sm[SM_LT + m0];
        const float* rb  = &sm[SM_R];
#pragma unroll 3
        for (int k = 0; k < 75; k++) {
            float4 a4 = *reinterpret_cast<const float4*>(ltb + k*128);
            ull pa0 = pk2(a4.x, a4.x), pa1 = pk2(a4.y, a4.y);
            ull pa2 = pk2(a4.z, a4.z), pa3 = pk2(a4.w, a4.w);
            const ull* rp = reinterpret_cast<const ull*>(rb + k*76 + n0);
#pragma unroll
            for (int j = 0; j < 5; j++) {
                ull r = rp[j];
                acc[0][j] = fma2(pa0, r, acc[0][j]);
                acc[1][j] = fma2(pa1, r, acc[1][j]);
                acc[2][j] = fma2(pa2, r, acc[2][j]);
                acc[3][j] = fma2(pa3, r, acc[3][j]);
            }
        }
        __syncthreads();
        if (kk < 3) {
            issue_R(kk+1); issue_LT(kk+1); cpa_commit();
        }
    }

    // X1 [128 m][75] into LT region
#pragma unroll
    for (int mi = 0; mi < 4; mi++) {
        float* xb = &sm[SM_LT + (m0 + mi)*75];
#pragma unroll
        for (int j = 0; j < 5; j++) {
            float lo, hi; unpk2(acc[mi][j], lo, hi);
            int nn = n0 + 2*j;
            if (nn < 75)     xb[nn]     = lo;
            if (nn + 1 < 75) xb[nn + 1] = hi;
        }
    }
    __syncthreads();

    // P4: fma2 epilogue
    if (tid < 160) {
        int it4 = tid / 40;
        int r   = tid - it4*40;
        int ot  = (r/5)*8, v0 = (r - (r/5)*5)*5;
#pragma unroll
        for (int pass = 0; pass < 2; pass++) {
            int it = it4 + (pass << 2);
            ull po[4][5];
#pragma unroll
            for (int a = 0; a < 4; a++)
#pragma unroll
                for (int b = 0; b < 5; b++) po[a][b] = 0ull;
            const float* x1b = &sm[SM_LT + it*16*75];
#pragma unroll
            for (int c = 0; c < 16; c++) {
#pragma unroll
                for (int win = 0; win < 3; win++) {
                    int kc = c*3 + win;
                    float4 wA = *reinterpret_cast<const float4*>(&sm[SM_WOT + kc*64 + ot]);
                    float4 wB = *reinterpret_cast<const float4*>(&sm[SM_WOT + kc*64 + ot + 4]);
                    ull pw[4] = {pk2(wA.x,wA.y), pk2(wA.z,wA.w),
                                 pk2(wB.x,wB.y), pk2(wB.z,wB.w)};
#pragma unroll
                    for (int i = 0; i < 5; i++) {
                        float xv = x1b[c*75 + win*25 + v0 + i];
                        ull px = pk2(xv, xv);
#pragma unroll
                        for (int a = 0; a < 4; a++)
                            po[a][i] = fma2(pw[a], px, po[a][i]);
                    }
                }
            }
#pragma unroll
            for (int a = 0; a < 4; a++) {
                int o0 = ot + a*2;
                float s0 = sm[SM_BN + o0],   h0 = sm[SM_BN + 64 + o0];
                float s1 = sm[SM_BN + o0+1], h1 = sm[SM_BN + 64 + o0+1];
                size_t b0 = ((size_t)(n*COV + o0)*TT + (t0 + it))*VV + v0;
                size_t b1 = b0 + (size_t)TT*VV;
#pragma unroll
                for (int i = 0; i < 5; i++) {
                    float lo, hi; unpk2(po[a][i], lo, hi);
                    out[b0 + i] = fmaxf(lo*s0 + h0 + x[b0 + i], 0.f);
                    out[b1 + i] = fmaxf(hi*s1 + h1 + x[b1 + i], 0.f);
                }
            }
        }
    }
}

// ============================================================
extern "C" void kernel_launch(void* const* d_in, const int* in_sizes, int n_in,
                              void* d_out, int out_size)
{
    (void)in_sizes; (void)n_in; (void)out_size;
    const float* x   = (const float*)d_in[0];
    const float* A   = (const float*)d_in[1];
    const float* PA  = (const float*)d_in[2];
    const float* Waw = (const float*)d_in[3];
    const float* Wab = (const float*)d_in[4];
    const float* Wdw = (const float*)d_in[5];
    const float* Wdb = (const float*)d_in[6];
    const float* Wcw = (const float*)d_in[7];
    const float* Wcb = (const float*)d_in[8];
    const float* Wow = (const float*)d_in[9];
    const float* Wob = (const float*)d_in[10];
    const float* gm  = (const float*)d_in[11];
    const float* bt  = (const float*)d_in[12];
    const float* mn  = (const float*)d_in[13];
    const float* vr  = (const float*)d_in[14];
    float* out = (float*)d_out;

    const size_t smem1 = (8192 + 5120 + 80) * sizeof(float);
    const size_t smem4 = SM_TOT * sizeof(float);
    cudaFuncSetAttribute(k1_conv80, cudaFuncAttributeMaxDynamicSharedMemorySize, (int)smem1);
    cudaFuncSetAttribute(k4_main,   cudaFuncAttributeMaxDynamicSharedMemorySize, (int)smem4);

    k0_init   <<<400, 256>>>(A, PA, Wdb, Wcb);
    k1_conv80 <<<dim3(TVTOT/K1_TV, NN), 320, smem1>>>(x, Waw, Wdw, Wdb, Wcw, Wcb);
    k2_gram   <<<dim3(KSPLIT, NN), 256>>>(Wab);
    k3a_reduce<<<dim3(22, NN), 256>>>();
    k3b_softmax<<<NN, 256>>>();
    k4_main   <<<NN*(TT/8), 256, smem4>>>(x, Wow, Wob, gm, bt, mn, vr, out);
}

// round 15
// speedup vs baseline: 1.0393x; 1.0393x over previous
#include <cuda_runtime.h>
#include <math.h>
#include <stdint.h>

#define NN 32
#define CC 64
#define TT 512
#define VV 25
#define C4V 16
#define W3V 75
#define COV 64
#define KSPLIT 32
#define KTOT (C4V*TT)
#define KCHUNK (KTOT/KSPLIT)  /* 256 */
#define TVTOT (TT*VV)
#define TVPAD 12850

typedef unsigned long long ull;

__device__ __forceinline__ ull pk2(float lo, float hi) {
    ull r; asm("mov.b64 %0, {%1,%2};" : "=l"(r) : "f"(lo), "f"(hi)); return r;
}
__device__ __forceinline__ ull fma2(ull a, ull b, ull c) {
    ull d; asm("fma.rn.f32x2 %0, %1, %2, %3;" : "=l"(d) : "l"(a), "l"(b), "l"(c)); return d;
}
__device__ __forceinline__ void unpk2(ull v, float& lo, float& hi) {
    asm("mov.b64 {%0,%1}, %2;" : "=f"(lo), "=f"(hi) : "l"(v));
}
__device__ __forceinline__ void cpa16(uint32_t s, const void* g) {
    asm volatile("cp.async.cg.shared.global [%0], [%1], 16;" :: "r"(s), "l"(g));
}
__device__ __forceinline__ void cpa_commit() {
    asm volatile("cp.async.commit_group;" ::: "memory");
}
template<int N> __device__ __forceinline__ void cpa_wait() {
    asm volatile("cp.async.wait_group %0;" :: "n"(N) : "memory");
}

__device__ float g_B[NN*C4V*TT*VV];
__device__ float g_L[(size_t)NN*TVPAD*64];
__device__ float g_Gpart[NN*KSPLIT*W3V*W3V];
__device__ float g_attp[NN*W3V*80];
__device__ float g_Aeff[3*W3V*80];

// ============================================================
__global__ void k0_init(const float* __restrict__ A, const float* __restrict__ PA,
                        const float* __restrict__ bd, const float* __restrict__ bc)
{
    int i = blockIdx.x*blockDim.x + threadIdx.x;
    if (i < 16875) {
        int k = i / 5625, r = i - k*5625;
        int w1 = r / 75, w2 = r - w1*75;
        g_Aeff[k*6000 + w1*80 + w2] = A[i] + PA[i];
    }
    if (i < 102400) {
        int ch = i & 63, rr = i >> 6;
        int n = rr / 50, row = rr - n*50;
        int tvp = (row < 25) ? row : (TVPAD - 25 + row - 25);
        float b = (ch < 16) ? bd[ch] : bc[ch-16];
        g_L[((size_t)n*TVPAD + tvp)*64 + ch] = b;
    }
}

// ============================================================
// K1 v2: x-splat fma2 (weight pairs load as ull directly)
// ============================================================
#define K1_TV 128
__global__ void __launch_bounds__(320) k1_conv80(
    const float* __restrict__ x,
    const float* __restrict__ Wa,
    const float* __restrict__ Wd, const float* __restrict__ bd,
    const float* __restrict__ Wc, const float* __restrict__ bc)
{
    extern __shared__ float sm[];
    float* sX = sm;
    float* sW = sm + 8192;
    float* sB = sm + 8192 + 5120;
    int tid = threadIdx.x;
    int n   = blockIdx.y;
    int tv0 = blockIdx.x * K1_TV;

    for (int i = tid; i < 5120; i += 320) {
        int c = i / 80, j = i - c*80;
        float w;
        if (j < 16)      w = Wd[j*CC + c];
        else if (j < 64) w = Wc[(j-16)*CC + c];
        else             w = Wa[(j-64)*CC + c];
        sW[i] = w;
    }
    if (tid < 80) sB[tid] = (tid < 16) ? bd[tid] : (tid < 64 ? bc[tid-16] : 0.f);

    const float* xp = x + (size_t)n*CC*TVTOT + tv0;
    for (int i = tid; i < 2048; i += 320) {
        int c = i >> 5, o = (i & 31) << 2;
        *reinterpret_cast<float4*>(&sX[c*128 + o]) =
            *reinterpret_cast<const float4*>(xp + (size_t)c*TVTOT + o);
    }
    __syncthreads();

    int jt = tid / 32;             // 0..9
    int tq = (tid & 31) << 2;
    ull acc2[4][4];
#pragma unroll
    for (int a = 0; a < 4; a++)
#pragma unroll
        for (int b = 0; b < 4; b++) acc2[a][b] = 0ull;

#pragma unroll 4
    for (int c = 0; c < 64; c++) {
        float4 xf = *reinterpret_cast<const float4*>(&sX[c*128 + tq]);
        ull px[4];
        px[0] = pk2(xf.x, xf.x); px[1] = pk2(xf.y, xf.y);
        px[2] = pk2(xf.z, xf.z); px[3] = pk2(xf.w, xf.w);
        ulonglong2 w01 = *reinterpret_cast<const ulonglong2*>(&sW[c*80 + jt*8]);
        ulonglong2 w23 = *reinterpret_cast<const ulonglong2*>(&sW[c*80 + jt*8 + 4]);
        ull wp[4] = {w01.x, w01.y, w23.x, w23.y};
#pragma unroll
        for (int p = 0; p < 4; p++)
#pragma unroll
            for (int t = 0; t < 4; t++)
                acc2[p][t] = fma2(wp[p], px[t], acc2[p][t]);
    }

    float val[8][4];
#pragma unroll
    for (int p = 0; p < 4; p++)
#pragma unroll
        for (int t = 0; t < 4; t++)
            unpk2(acc2[p][t], val[2*p][t], val[2*p+1][t]);

    int j0 = jt*8;
    if (j0 < 64) {
        float b[8];
#pragma unroll
        for (int jj = 0; jj < 8; jj++) b[jj] = sB[j0+jj];
        float* gl = g_L + ((size_t)n*TVPAD + 25 + tv0 + tq)*64 + j0;
#pragma unroll
        for (int t4 = 0; t4 < 4; t4++) {
            float4 r0 = make_float4(val[0][t4]+b[0], val[1][t4]+b[1],
                                    val[2][t4]+b[2], val[3][t4]+b[3]);
            float4 r1 = make_float4(val[4][t4]+b[4], val[5][t4]+b[5],
                                    val[6][t4]+b[6], val[7][t4]+b[7]);
            *reinterpret_cast<float4*>(gl + (size_t)t4*64)     = r0;
            *reinterpret_cast<float4*>(gl + (size_t)t4*64 + 4) = r1;
        }
    } else {
#pragma unroll
        for (int jj = 0; jj < 8; jj++) {
            int o = j0 - 64 + jj;
            float4 r = make_float4(val[jj][0], val[jj][1], val[jj][2], val[jj][3]);
            *reinterpret_cast<float4*>(g_B + (size_t)(n*C4V + o)*TVTOT + tv0 + tq) = r;
        }
    }
}

// ============================================================
// K2 (R13 version): symmetric Gram — 120 upper-triangle 5x5 tiles.
// ============================================================
__global__ void k2_gram(const float* __restrict__ ba)
{
    __shared__ __align__(16) float tile[W3V*34];
    int n  = blockIdx.y;
    int ks = blockIdx.x;
    int tid = threadIdx.x;

    int tw1 = 0, tw2 = 0;
    if (tid < 120) {
        int rem = tid, i = 0;
        while (rem >= 15 - i) { rem -= 15 - i; i++; }
        tw1 = i; tw2 = i + rem;
    }

    ull acc2[5][5];
#pragma unroll
    for (int i = 0; i < 5; i++)
#pragma unroll
        for (int j = 0; j < 5; j++) acc2[i][j] = 0ull;

    int k0 = ks * KCHUNK;
    for (int kt = 0; kt < KCHUNK; kt += 32) {
        for (int i = tid; i < 32*W3V; i += 256) {
            int r = i / W3V, w = i - r*W3V;
            int k = k0 + kt + r;
            int o = k >> 9, t = k & 511;
            int win = w / VV, v = w - win*VV;
            int ts = t + win - 1;
            float val = ba[o];
            if (ts >= 0 && ts < TT)
                val += g_B[((size_t)(n*C4V + o)*TT + ts)*VV + v];
            tile[w*34 + r] = val;
        }
        __syncthreads();
        if (tid < 120) {
            const float* ta = &tile[(tw1*5)*34];
            const float* tb = &tile[(tw2*5)*34];
#pragma unroll 2
            for (int rp = 0; rp < 16; rp++) {
                ull pa[5], pb[5];
#pragma unroll
                for (int i = 0; i < 5; i++)
                    pa[i] = *reinterpret_cast<const ull*>(ta + i*34 + 2*rp);
#pragma unroll
                for (int j = 0; j < 5; j++)
                    pb[j] = *reinterpret_cast<const ull*>(tb + j*34 + 2*rp);
#pragma unroll
                for (int i = 0; i < 5; i++)
#pragma unroll
                    for (int j = 0; j < 5; j++)
                        acc2[i][j] = fma2(pa[i], pb[j], acc2[i][j]);
            }
        }
        __syncthreads();
    }
    if (tid < 120) {
        float* gp = g_Gpart + (size_t)(n*KSPLIT + ks)*W3V*W3V;
#pragma unroll
        for (int i = 0; i < 5; i++)
#pragma unroll
            for (int j = 0; j < 5; j++) {
                float lo, hi; unpk2(acc2[i][j], lo, hi);
                float v = lo + hi;
                gp[(tw1*5+i)*W3V + (tw2*5+j)] = v;
                gp[(tw2*5+j)*W3V + (tw1*5+i)] = v;
            }
    }
}

// ============================================================
// K3a: parallel reduce of 32 partials into the p=0 slice.
// ============================================================
__global__ void k3a_reduce()
{
    int n = blockIdx.y;
    int i = blockIdx.x*256 + threadIdx.x;
    if (i >= W3V*W3V) return;
    const float* gp = g_Gpart + (size_t)n*KSPLIT*W3V*W3V + i;
    float s = 0.f;
#pragma unroll 8
    for (int p = 0; p < KSPLIT; p++)
        s += gp[(size_t)p*W3V*W3V];
    g_Gpart[(size_t)n*KSPLIT*W3V*W3V + i] = s;
}

// ============================================================
// K3b: softmax on reduced matrix -> padded att
// ============================================================
__global__ void k3b_softmax()
{
    __shared__ float sG[W3V*W3V];
    int n = blockIdx.x, tid = threadIdx.x;
    const float* gr = g_Gpart + (size_t)n*KSPLIT*W3V*W3V;
    for (int i = tid; i < W3V*W3V; i += 256)
        sG[i] = gr[i] * (1.0f / (float)W3V);
    __syncthreads();
    if (tid < W3V) {
        float mx = -1e30f;
        for (int w1 = 0; w1 < W3V; w1++) mx = fmaxf(mx, sG[w1*W3V + tid]);
        float sum = 0.f;
        for (int w1 = 0; w1 < W3V; w1++) {
            float e = expf(sG[w1*W3V + tid] - mx);
            sG[w1*W3V + tid] = e;
            sum += e;
        }
        float inv = 1.f / sum;
        for (int w1 = 0; w1 < W3V; w1++)
            g_attp[(size_t)n*6000 + w1*80 + tid] = sG[w1*W3V + tid] * inv;
    }
}

// ============================================================
// K4 v12 (unchanged): TPB=8, 256 threads, 3 blocks/SM.
// ============================================================
#define SM_R    0       /* [75][76] = 5700 */
#define SM_LT   5700    /* [75][128] = 9600 ; X1 union after loop */
#define SM_WOT  15300   /* 3072 */
#define SM_BN   18372   /* 128 */
#define SM_TOT  18500   /* 74000 B */

__global__ void __launch_bounds__(256, 3) k4_main(
    const float* __restrict__ x,
    const float* __restrict__ Wo,  const float* __restrict__ bo,
    const float* __restrict__ gma, const float* __restrict__ bta,
    const float* __restrict__ mean,const float* __restrict__ var,
    float* __restrict__ out)
{
    extern __shared__ float sm[];
    uint32_t sbase = (uint32_t)__cvta_generic_to_shared(sm);
    int tid = threadIdx.x;
    int n  = blockIdx.x >> 6;
    int t0 = (blockIdx.x & 63) << 3;

    for (int i = tid; i < 3072; i += 256) {
        int kc = i >> 6, o = i & 63;
        sm[SM_WOT + i] = Wo[o*48 + kc];
    }
    if (tid < 64) {
        float sc = gma[tid] * rsqrtf(var[tid] + 1e-5f);
        sm[SM_BN + tid]      = sc;
        sm[SM_BN + 64 + tid] = (bo[tid] - mean[tid])*sc + bta[tid];
    }

    const float* gl = g_L + (size_t)n*TVPAD*64;

    auto issue_R = [&](int kk) {
        uint32_t rdst = sbase + SM_R*4;
        const float* rsrc = (kk == 0) ? (g_attp + (size_t)n*6000)
                                      : (g_Aeff + (size_t)(kk-1)*6000);
        for (int i = tid; i < 1425; i += 256) {
            int k = i / 19, q = (i - k*19) << 2;
            cpa16(rdst + (k*76 + q)*4, rsrc + k*80 + q);
        }
    };
    auto issue_LT = [&](int kk) {
        uint32_t ldst = sbase + SM_LT*4;
        for (int i = tid; i < 2400; i += 256) {
            int seg = i >> 2, q = (i & 3) << 2;
            int k  = seg >> 3, it = seg & 7;
            int win = (k*41) >> 10;
            int v   = k - win*25;
            int tvp = (t0 + it + win)*25 + v;
            cpa16(ldst + (k*128 + it*16 + q)*4,
                  gl + ((size_t)tvp << 6) + kk*16 + q);
        }
    };

    int w = tid >> 5, l = tid & 31;
    int mt = ((w >> 1) << 3) + (l >> 2);
    int nt = ((w & 1) << 2) + (l & 3);
    int m0 = mt << 2;
    int n0 = nt * 10;

    ull acc[4][5];
#pragma unroll
    for (int a = 0; a < 4; a++)
#pragma unroll
        for (int j = 0; j < 5; j++) acc[a][j] = 0ull;

    issue_R(0); issue_LT(0); cpa_commit();

    for (int kk = 0; kk < 4; kk++) {
        cpa_wait<0>();
        __syncthreads();

        const float* ltb = &sm[SM_LT + m0];
        const float* rb  = &sm[SM_R];
#pragma unroll 3
        for (int k = 0; k < 75; k++) {
            float4 a4 = *reinterpret_cast<const float4*>(ltb + k*128);
            ull pa0 = pk2(a4.x, a4.x), pa1 = pk2(a4.y, a4.y);
            ull pa2 = pk2(a4.z, a4.z), pa3 = pk2(a4.w, a4.w);
            const ull* rp = reinterpret_cast<const ull*>(rb + k*76 + n0);
#pragma unroll
            for (int j = 0; j < 5; j++) {
                ull r = rp[j];
                acc[0][j] = fma2(pa0, r, acc[0][j]);
                acc[1][j] = fma2(pa1, r, acc[1][j]);
                acc[2][j] = fma2(pa2, r, acc[2][j]);
                acc[3][j] = fma2(pa3, r, acc[3][j]);
            }
        }
        __syncthreads();
        if (kk < 3) {
            issue_R(kk+1); issue_LT(kk+1); cpa_commit();
        }
    }

    // X1 [128 m][75] into LT region
#pragma unroll
    for (int mi = 0; mi < 4; mi++) {
        float* xb = &sm[SM_LT + (m0 + mi)*75];
#pragma unroll
        for (int j = 0; j < 5; j++) {
            float lo, hi; unpk2(acc[mi][j], lo, hi);
            int nn = n0 + 2*j;
            if (nn < 75)     xb[nn]     = lo;
            if (nn + 1 < 75) xb[nn + 1] = hi;
        }
    }
    __syncthreads();

    // P4: fma2 epilogue
    if (tid < 160) {
        int it4 = tid / 40;
        int r   = tid - it4*40;
        int ot  = (r/5)*8, v0 = (r - (r/5)*5)*5;
#pragma unroll
        for (int pass = 0; pass < 2; pass++) {
            int it = it4 + (pass << 2);
            ull po[4][5];
#pragma unroll
            for (int a = 0; a < 4; a++)
#pragma unroll
                for (int b = 0; b < 5; b++) po[a][b] = 0ull;
            const float* x1b = &sm[SM_LT + it*16*75];
#pragma unroll
            for (int c = 0; c < 16; c++) {
#pragma unroll
                for (int win = 0; win < 3; win++) {
                    int kc = c*3 + win;
                    float4 wA = *reinterpret_cast<const float4*>(&sm[SM_WOT + kc*64 + ot]);
                    float4 wB = *reinterpret_cast<const float4*>(&sm[SM_WOT + kc*64 + ot + 4]);
                    ull pw[4] = {pk2(wA.x,wA.y), pk2(wA.z,wA.w),
                                 pk2(wB.x,wB.y), pk2(wB.z,wB.w)};
#pragma unroll
                    for (int i = 0; i < 5; i++) {
                        float xv = x1b[c*75 + win*25 + v0 + i];
                        ull px = pk2(xv, xv);
#pragma unroll
                        for (int a = 0; a < 4; a++)
                            po[a][i] = fma2(pw[a], px, po[a][i]);
                    }
                }
            }
#pragma unroll
            for (int a = 0; a < 4; a++) {
                int o0 = ot + a*2;
                float s0 = sm[SM_BN + o0],   h0 = sm[SM_BN + 64 + o0];
                float s1 = sm[SM_BN + o0+1], h1 = sm[SM_BN + 64 + o0+1];
                size_t b0 = ((size_t)(n*COV + o0)*TT + (t0 + it))*VV + v0;
                size_t b1 = b0 + (size_t)TT*VV;
#pragma unroll
                for (int i = 0; i < 5; i++) {
                    float lo, hi; unpk2(po[a][i], lo, hi);
                    out[b0 + i] = fmaxf(lo*s0 + h0 + x[b0 + i], 0.f);
                    out[b1 + i] = fmaxf(hi*s1 + h1 + x[b1 + i], 0.f);
                }
            }
        }
    }
}

// ============================================================
extern "C" void kernel_launch(void* const* d_in, const int* in_sizes, int n_in,
                              void* d_out, int out_size)
{
    (void)in_sizes; (void)n_in; (void)out_size;
    const float* x   = (const float*)d_in[0];
    const float* A   = (const float*)d_in[1];
    const float* PA  = (const float*)d_in[2];
    const float* Waw = (const float*)d_in[3];
    const float* Wab = (const float*)d_in[4];
    const float* Wdw = (const float*)d_in[5];
    const float* Wdb = (const float*)d_in[6];
    const float* Wcw = (const float*)d_in[7];
    const float* Wcb = (const float*)d_in[8];
    const float* Wow = (const float*)d_in[9];
    const float* Wob = (const float*)d_in[10];
    const float* gm  = (const float*)d_in[11];
    const float* bt  = (const float*)d_in[12];
    const float* mn  = (const float*)d_in[13];
    const float* vr  = (const float*)d_in[14];
    float* out = (float*)d_out;

    const size_t smem1 = (8192 + 5120 + 80) * sizeof(float);
    const size_t smem4 = SM_TOT * sizeof(float);
    cudaFuncSetAttribute(k1_conv80, cudaFuncAttributeMaxDynamicSharedMemorySize, (int)smem1);
    cudaFuncSetAttribute(k4_main,   cudaFuncAttributeMaxDynamicSharedMemorySize, (int)smem4);

    k0_init   <<<400, 256>>>(A, PA, Wdb, Wcb);
    k1_conv80 <<<dim3(TVTOT/K1_TV, NN), 320, smem1>>>(x, Waw, Wdw, Wdb, Wcw, Wcb);
    k2_gram   <<<dim3(KSPLIT, NN), 256>>>(Wab);
    k3a_reduce<<<dim3(22, NN), 256>>>();
    k3b_softmax<<<NN, 256>>>();
    k4_main   <<<NN*(TT/8), 256, smem4>>>(x, Wow, Wob, gm, bt, mn, vr, out);
}

// round 16
// speedup vs baseline: 1.0815x; 1.0406x over previous
#include <cuda_runtime.h>
#include <math.h>
#include <stdint.h>

#define NN 32
#define CC 64
#define TT 512
#define VV 25
#define C4V 16
#define W3V 75
#define COV 64
#define KSPLIT 32
#define KTOT (C4V*TT)
#define KCHUNK (KTOT/KSPLIT)  /* 256 */
#define TVTOT (TT*VV)
#define TVPAD 12850

typedef unsigned long long ull;

__device__ __forceinline__ ull pk2(float lo, float hi) {
    ull r; asm("mov.b64 %0, {%1,%2};" : "=l"(r) : "f"(lo), "f"(hi)); return r;
}
__device__ __forceinline__ ull fma2(ull a, ull b, ull c) {
    ull d; asm("fma.rn.f32x2 %0, %1, %2, %3;" : "=l"(d) : "l"(a), "l"(b), "l"(c)); return d;
}
__device__ __forceinline__ void unpk2(ull v, float& lo, float& hi) {
    asm("mov.b64 {%0,%1}, %2;" : "=f"(lo), "=f"(hi) : "l"(v));
}
__device__ __forceinline__ void cpa16(uint32_t s, const void* g) {
    asm volatile("cp.async.cg.shared.global [%0], [%1], 16;" :: "r"(s), "l"(g));
}
__device__ __forceinline__ void cpa4(uint32_t s, const void* g) {
    asm volatile("cp.async.ca.shared.global [%0], [%1], 4;" :: "r"(s), "l"(g));
}
__device__ __forceinline__ void cpa_commit() {
    asm volatile("cp.async.commit_group;" ::: "memory");
}
template<int N> __device__ __forceinline__ void cpa_wait() {
    asm volatile("cp.async.wait_group %0;" :: "n"(N) : "memory");
}

__device__ float g_B[NN*C4V*TT*VV];          // conv_a(x) + bias (bias baked in k1)
__device__ float g_L[(size_t)NN*TVPAD*64];
__device__ float g_Gpart[NN*KSPLIT*W3V*W3V];
__device__ float g_attp[NN*W3V*80];
__device__ float g_Aeff[3*W3V*80];

// ============================================================
__global__ void k0_init(const float* __restrict__ A, const float* __restrict__ PA,
                        const float* __restrict__ bd, const float* __restrict__ bc)
{
    int i = blockIdx.x*blockDim.x + threadIdx.x;
    if (i < 16875) {
        int k = i / 5625, r = i - k*5625;
        int w1 = r / 75, w2 = r - w1*75;
        g_Aeff[k*6000 + w1*80 + w2] = A[i] + PA[i];
    }
    if (i < 102400) {
        int ch = i & 63, rr = i >> 6;
        int n = rr / 50, row = rr - n*50;
        int tvp = (row < 25) ? row : (TVPAD - 25 + row - 25);
        float b = (ch < 16) ? bd[ch] : bc[ch-16];
        g_L[((size_t)n*TVPAD + tvp)*64 + ch] = b;
    }
}

// ============================================================
// K1 v3: x-splat fma2; conv_a bias baked into g_B store.
// ============================================================
#define K1_TV 128
__global__ void __launch_bounds__(320) k1_conv80(
    const float* __restrict__ x,
    const float* __restrict__ Wa, const float* __restrict__ ba,
    const float* __restrict__ Wd, const float* __restrict__ bd,
    const float* __restrict__ Wc, const float* __restrict__ bc)
{
    extern __shared__ float sm[];
    float* sX = sm;
    float* sW = sm + 8192;
    float* sB = sm + 8192 + 5120;
    int tid = threadIdx.x;
    int n   = blockIdx.y;
    int tv0 = blockIdx.x * K1_TV;

    for (int i = tid; i < 5120; i += 320) {
        int c = i / 80, j = i - c*80;
        float w;
        if (j < 16)      w = Wd[j*CC + c];
        else if (j < 64) w = Wc[(j-16)*CC + c];
        else             w = Wa[(j-64)*CC + c];
        sW[i] = w;
    }
    if (tid < 80) sB[tid] = (tid < 16) ? bd[tid] : (tid < 64 ? bc[tid-16] : ba[tid-64]);

    const float* xp = x + (size_t)n*CC*TVTOT + tv0;
    for (int i = tid; i < 2048; i += 320) {
        int c = i >> 5, o = (i & 31) << 2;
        *reinterpret_cast<float4*>(&sX[c*128 + o]) =
            *reinterpret_cast<const float4*>(xp + (size_t)c*TVTOT + o);
    }
    __syncthreads();

    int jt = tid / 32;
    int tq = (tid & 31) << 2;
    ull acc2[4][4];
#pragma unroll
    for (int a = 0; a < 4; a++)
#pragma unroll
        for (int b = 0; b < 4; b++) acc2[a][b] = 0ull;

#pragma unroll 4
    for (int c = 0; c < 64; c++) {
        float4 xf = *reinterpret_cast<const float4*>(&sX[c*128 + tq]);
        ull px[4];
        px[0] = pk2(xf.x, xf.x); px[1] = pk2(xf.y, xf.y);
        px[2] = pk2(xf.z, xf.z); px[3] = pk2(xf.w, xf.w);
        ulonglong2 w01 = *reinterpret_cast<const ulonglong2*>(&sW[c*80 + jt*8]);
        ulonglong2 w23 = *reinterpret_cast<const ulonglong2*>(&sW[c*80 + jt*8 + 4]);
        ull wp[4] = {w01.x, w01.y, w23.x, w23.y};
#pragma unroll
        for (int p = 0; p < 4; p++)
#pragma unroll
            for (int t = 0; t < 4; t++)
                acc2[p][t] = fma2(wp[p], px[t], acc2[p][t]);
    }

    float val[8][4];
#pragma unroll
    for (int p = 0; p < 4; p++)
#pragma unroll
        for (int t = 0; t < 4; t++)
            unpk2(acc2[p][t], val[2*p][t], val[2*p+1][t]);

    int j0 = jt*8;
    if (j0 < 64) {
        float b[8];
#pragma unroll
        for (int jj = 0; jj < 8; jj++) b[jj] = sB[j0+jj];
        float* gl = g_L + ((size_t)n*TVPAD + 25 + tv0 + tq)*64 + j0;
#pragma unroll
        for (int t4 = 0; t4 < 4; t4++) {
            float4 r0 = make_float4(val[0][t4]+b[0], val[1][t4]+b[1],
                                    val[2][t4]+b[2], val[3][t4]+b[3]);
            float4 r1 = make_float4(val[4][t4]+b[4], val[5][t4]+b[5],
                                    val[6][t4]+b[6], val[7][t4]+b[7]);
            *reinterpret_cast<float4*>(gl + (size_t)t4*64)     = r0;
            *reinterpret_cast<float4*>(gl + (size_t)t4*64 + 4) = r1;
        }
    } else {
        float b[8];
#pragma unroll
        for (int jj = 0; jj < 8; jj++) b[jj] = sB[j0+jj];
#pragma unroll
        for (int jj = 0; jj < 8; jj++) {
            int o = j0 - 64 + jj;
            float4 r = make_float4(val[jj][0]+b[jj], val[jj][1]+b[jj],
                                   val[jj][2]+b[jj], val[jj][3]+b[jj]);
            *reinterpret_cast<float4*>(g_B + (size_t)(n*C4V + o)*TVTOT + tv0 + tq) = r;
        }
    }
}

// ============================================================
// K2 v5: symmetric Gram (120 upper-tri 5x5 tiles) with
// cp.async double-buffered tile staging (bias pre-baked in g_B;
// out-of-range rows = bias via STS).
// ============================================================
__global__ void k2_gram(const float* __restrict__ ba)
{
    __shared__ __align__(16) float tile[2][W3V*34];
    int n  = blockIdx.y;
    int ks = blockIdx.x;
    int tid = threadIdx.x;
    uint32_t sbase = (uint32_t)__cvta_generic_to_shared(&tile[0][0]);

    int tw1 = 0, tw2 = 0;
    if (tid < 120) {
        int rem = tid, i = 0;
        while (rem >= 15 - i) { rem -= 15 - i; i++; }
        tw1 = i; tw2 = i + rem;
    }

    ull acc2[5][5];
#pragma unroll
    for (int i = 0; i < 5; i++)
#pragma unroll
        for (int j = 0; j < 5; j++) acc2[i][j] = 0ull;

    int k0 = ks * KCHUNK;

    auto issue_stage = [&](int s, int buf) {
        int kt = s * 32;
        uint32_t tb = sbase + (uint32_t)(buf * (W3V*34) * 4);
        for (int i = tid; i < 32*W3V; i += 256) {
            int r = i / W3V, w = i - r*W3V;
            int k = k0 + kt + r;
            int o = k >> 9, t = k & 511;
            int win = w / VV, v = w - win*VV;
            int ts = t + win - 1;
            uint32_t dst = tb + (uint32_t)(w*34 + r)*4;
            if (ts >= 0 && ts < TT)
                cpa4(dst, g_B + ((size_t)(n*C4V + o)*TT + ts)*VV + v);
            else {
                float bias = ba[o];
                asm volatile("st.shared.f32 [%0], %1;" :: "r"(dst), "f"(bias));
            }
        }
    };

    issue_stage(0, 0); cpa_commit();

    const int NSTAGE = KCHUNK/32;   /* 8 */
    for (int s = 0; s < NSTAGE; s++) {
        int buf = s & 1;
        if (s < NSTAGE-1) {
            issue_stage(s+1, 1-buf); cpa_commit();
            cpa_wait<1>();
        } else {
            cpa_wait<0>();
        }
        __syncthreads();
        if (tid < 120) {
            const float* ta = &tile[buf][(tw1*5)*34];
            const float* tb = &tile[buf][(tw2*5)*34];
#pragma unroll 2
            for (int rp = 0; rp < 16; rp++) {
                ull pa[5], pb[5];
#pragma unroll
                for (int i = 0; i < 5; i++)
                    pa[i] = *reinterpret_cast<const ull*>(ta + i*34 + 2*rp);
#pragma unroll
                for (int j = 0; j < 5; j++)
                    pb[j] = *reinterpret_cast<const ull*>(tb + j*34 + 2*rp);
#pragma unroll
                for (int i = 0; i < 5; i++)
#pragma unroll
                    for (int j = 0; j < 5; j++)
                        acc2[i][j] = fma2(pa[i], pb[j], acc2[i][j]);
            }
        }
        __syncthreads();
    }
    if (tid < 120) {
        float* gp = g_Gpart + (size_t)(n*KSPLIT + ks)*W3V*W3V;
#pragma unroll
        for (int i = 0; i < 5; i++)
#pragma unroll
            for (int j = 0; j < 5; j++) {
                float lo, hi; unpk2(acc2[i][j], lo, hi);
                float v = lo + hi;
                gp[(tw1*5+i)*W3V + (tw2*5+j)] = v;
                gp[(tw2*5+j)*W3V + (tw1*5+i)] = v;
            }
    }
}

// ============================================================
// K3a: parallel reduce of 32 partials into the p=0 slice.
// ============================================================
__global__ void k3a_reduce()
{
    int n = blockIdx.y;
    int i = blockIdx.x*256 + threadIdx.x;
    if (i >= W3V*W3V) return;
    const float* gp = g_Gpart + (size_t)n*KSPLIT*W3V*W3V + i;
    float s = 0.f;
#pragma unroll 8
    for (int p = 0; p < KSPLIT; p++)
        s += gp[(size_t)p*W3V*W3V];
    g_Gpart[(size_t)n*KSPLIT*W3V*W3V + i] = s;
}

// ============================================================
// K3b: softmax on reduced matrix -> padded att
// ============================================================
__global__ void k3b_softmax()
{
    __shared__ float sG[W3V*W3V];
    int n = blockIdx.x, tid = threadIdx.x;
    const float* gr = g_Gpart + (size_t)n*KSPLIT*W3V*W3V;
    for (int i = tid; i < W3V*W3V; i += 256)
        sG[i] = gr[i] * (1.0f / (float)W3V);
    __syncthreads();
    if (tid < W3V) {
        float mx = -1e30f;
        for (int w1 = 0; w1 < W3V; w1++) mx = fmaxf(mx, sG[w1*W3V + tid]);
        float sum = 0.f;
        for (int w1 = 0; w1 < W3V; w1++) {
            float e = expf(sG[w1*W3V + tid] - mx);
            sG[w1*W3V + tid] = e;
            sum += e;
        }
        float inv = 1.f / sum;
        for (int w1 = 0; w1 < W3V; w1++)
            g_attp[(size_t)n*6000 + w1*80 + tid] = sG[w1*W3V + tid] * inv;
    }
}

// ============================================================
// K4 v12 (unchanged): TPB=8, 256 threads, 3 blocks/SM.
// ============================================================
#define SM_R    0       /* [75][76] = 5700 */
#define SM_LT   5700    /* [75][128] = 9600 ; X1 union after loop */
#define SM_WOT  15300   /* 3072 */
#define SM_BN   18372   /* 128 */
#define SM_TOT  18500   /* 74000 B */

__global__ void __launch_bounds__(256, 3) k4_main(
    const float* __restrict__ x,
    const float* __restrict__ Wo,  const float* __restrict__ bo,
    const float* __restrict__ gma, const float* __restrict__ bta,
    const float* __restrict__ mean,const float* __restrict__ var,
    float* __restrict__ out)
{
    extern __shared__ float sm[];
    uint32_t sbase = (uint32_t)__cvta_generic_to_shared(sm);
    int tid = threadIdx.x;
    int n  = blockIdx.x >> 6;
    int t0 = (blockIdx.x & 63) << 3;

    for (int i = tid; i < 3072; i += 256) {
        int kc = i >> 6, o = i & 63;
        sm[SM_WOT + i] = Wo[o*48 + kc];
    }
    if (tid < 64) {
        float sc = gma[tid] * rsqrtf(var[tid] + 1e-5f);
        sm[SM_BN + tid]      = sc;
        sm[SM_BN + 64 + tid] = (bo[tid] - mean[tid])*sc + bta[tid];
    }

    const float* gl = g_L + (size_t)n*TVPAD*64;

    auto issue_R = [&](int kk) {
        uint32_t rdst = sbase + SM_R*4;
        const float* rsrc = (kk == 0) ? (g_attp + (size_t)n*6000)
                                      : (g_Aeff + (size_t)(kk-1)*6000);
        for (int i = tid; i < 1425; i += 256) {
            int k = i / 19, q = (i - k*19) << 2;
            cpa16(rdst + (k*76 + q)*4, rsrc + k*80 + q);
        }
    };
    auto issue_LT = [&](int kk) {
        uint32_t ldst = sbase + SM_LT*4;
        for (int i = tid; i < 2400; i += 256) {
            int seg = i >> 2, q = (i & 3) << 2;
            int k  = seg >> 3, it = seg & 7;
            int win = (k*41) >> 10;
            int v   = k - win*25;
            int tvp = (t0 + it + win)*25 + v;
            cpa16(ldst + (k*128 + it*16 + q)*4,
                  gl + ((size_t)tvp << 6) + kk*16 + q);
        }
    };

    int w = tid >> 5, l = tid & 31;
    int mt = ((w >> 1) << 3) + (l >> 2);
    int nt = ((w & 1) << 2) + (l & 3);
    int m0 = mt << 2;
    int n0 = nt * 10;

    ull acc[4][5];
#pragma unroll
    for (int a = 0; a < 4; a++)
#pragma unroll
        for (int j = 0; j < 5; j++) acc[a][j] = 0ull;

    issue_R(0); issue_LT(0); cpa_commit();

    for (int kk = 0; kk < 4; kk++) {
        cpa_wait<0>();
        __syncthreads();

        const float* ltb = &sm[SM_LT + m0];
        const float* rb  = &sm[SM_R];
#pragma unroll 3
        for (int k = 0; k < 75; k++) {
            float4 a4 = *reinterpret_cast<const float4*>(ltb + k*128);
            ull pa0 = pk2(a4.x, a4.x), pa1 = pk2(a4.y, a4.y);
            ull pa2 = pk2(a4.z, a4.z), pa3 = pk2(a4.w, a4.w);
            const ull* rp = reinterpret_cast<const ull*>(rb + k*76 + n0);
#pragma unroll
            for (int j = 0; j < 5; j++) {
                ull r = rp[j];
                acc[0][j] = fma2(pa0, r, acc[0][j]);
                acc[1][j] = fma2(pa1, r, acc[1][j]);
                acc[2][j] = fma2(pa2, r, acc[2][j]);
                acc[3][j] = fma2(pa3, r, acc[3][j]);
            }
        }
        __syncthreads();
        if (kk < 3) {
            issue_R(kk+1); issue_LT(kk+1); cpa_commit();
        }
    }

    // X1 [128 m][75] into LT region
#pragma unroll
    for (int mi = 0; mi < 4; mi++) {
        float* xb = &sm[SM_LT + (m0 + mi)*75];
#pragma unroll
        for (int j = 0; j < 5; j++) {
            float lo, hi; unpk2(acc[mi][j], lo, hi);
            int nn = n0 + 2*j;
            if (nn < 75)     xb[nn]     = lo;
            if (nn + 1 < 75) xb[nn + 1] = hi;
        }
    }
    __syncthreads();

    // P4: fma2 epilogue
    if (tid < 160) {
        int it4 = tid / 40;
        int r   = tid - it4*40;
        int ot  = (r/5)*8, v0 = (r - (r/5)*5)*5;
#pragma unroll
        for (int pass = 0; pass < 2; pass++) {
            int it = it4 + (pass << 2);
            ull po[4][5];
#pragma unroll
            for (int a = 0; a < 4; a++)
#pragma unroll
                for (int b = 0; b < 5; b++) po[a][b] = 0ull;
            const float* x1b = &sm[SM_LT + it*16*75];
#pragma unroll
            for (int c = 0; c < 16; c++) {
#pragma unroll
                for (int win = 0; win < 3; win++) {
                    int kc = c*3 + win;
                    float4 wA = *reinterpret_cast<const float4*>(&sm[SM_WOT + kc*64 + ot]);
                    float4 wB = *reinterpret_cast<const float4*>(&sm[SM_WOT + kc*64 + ot + 4]);
                    ull pw[4] = {pk2(wA.x,wA.y), pk2(wA.z,wA.w),
                                 pk2(wB.x,wB.y), pk2(wB.z,wB.w)};
#pragma unroll
                    for (int i = 0; i < 5; i++) {
                        float xv = x1b[c*75 + win*25 + v0 + i];
                        ull px = pk2(xv, xv);
#pragma unroll
                        for (int a = 0; a < 4; a++)
                            po[a][i] = fma2(pw[a], px, po[a][i]);
                    }
                }
            }
#pragma unroll
            for (int a = 0; a < 4; a++) {
                int o0 = ot + a*2;
                float s0 = sm[SM_BN + o0],   h0 = sm[SM_BN + 64 + o0];
                float s1 = sm[SM_BN + o0+1], h1 = sm[SM_BN + 64 + o0+1];
                size_t b0 = ((size_t)(n*COV + o0)*TT + (t0 + it))*VV + v0;
                size_t b1 = b0 + (size_t)TT*VV;
#pragma unroll
                for (int i = 0; i < 5; i++) {
                    float lo, hi; unpk2(po[a][i], lo, hi);
                    out[b0 + i] = fmaxf(lo*s0 + h0 + x[b0 + i], 0.f);
                    out[b1 + i] = fmaxf(hi*s1 + h1 + x[b1 + i], 0.f);
                }
            }
        }
    }
}

// ============================================================
extern "C" void kernel_launch(void* const* d_in, const int* in_sizes, int n_in,
                              void* d_out, int out_size)
{
    (void)in_sizes; (void)n_in; (void)out_size;
    const float* x   = (const float*)d_in[0];
    const float* A   = (const float*)d_in[1];
    const float* PA  = (const float*)d_in[2];
    const float* Waw = (const float*)d_in[3];
    const float* Wab = (const float*)d_in[4];
    const float* Wdw = (const float*)d_in[5];
    const float* Wdb = (const float*)d_in[6];
    const float* Wcw = (const float*)d_in[7];
    const float* Wcb = (const float*)d_in[8];
    const float* Wow = (const float*)d_in[9];
    const float* Wob = (const float*)d_in[10];
    const float* gm  = (const float*)d_in[11];
    const float* bt  = (const float*)d_in[12];
    const float* mn  = (const float*)d_in[13];
    const float* vr  = (const float*)d_in[14];
    float* out = (float*)d_out;

    const size_t smem1 = (8192 + 5120 + 80) * sizeof(float);
    const size_t smem4 = SM_TOT * sizeof(float);
    cudaFuncSetAttribute(k1_conv80, cudaFuncAttributeMaxDynamicSharedMemorySize, (int)smem1);
    cudaFuncSetAttribute(k4_main,   cudaFuncAttributeMaxDynamicSharedMemorySize, (int)smem4);

    k0_init   <<<400, 256>>>(A, PA, Wdb, Wcb);
    k1_conv80 <<<dim3(TVTOT/K1_TV, NN), 320, smem1>>>(x, Waw, Wab, Wdw, Wdb, Wcw, Wcb);
    k2_gram   <<<dim3(KSPLIT, NN), 256>>>(Wab);
    k3a_reduce<<<dim3(22, NN), 256>>>();
    k3b_softmax<<<NN, 256>>>();
    k4_main   <<<NN*(TT/8), 256, smem4>>>(x, Wow, Wob, gm, bt, mn, vr, out);
}